// round 16
// baseline (speedup 1.0000x reference)
#include <cuda_runtime.h>

// Problem constants
#define S    8192
#define D    768
#define D4   (D/4)        // 192 float4 per row
#define NA   256
#define NO   256
#define NSP  (NA+NO)      // 512 spans
#define NP   (NA*NO)      // 65536 pairs
#define NCAT 13
#define NPOL 3
#define NK   18           // 2 valid + 13 cat + 3 pol partials per span

// Output layout (flattened tuple, fp32)
#define OFF_AID ((size_t)NP * (2*D))
#define OFF_OID (OFF_AID + NP)
#define OFF_CAT (OFF_OID + NP)
#define OFF_POL (OFF_CAT + (size_t)NP*NCAT)
#define OFF_MSK (OFF_POL + (size_t)NP*NPOL)

// Scratch (allocation-free rule: device globals)
__device__ float g_rep[NSP * D];       // aspect rows [0,256), opinion rows [256,512)
__device__ float g_part[NSP * NK];     // per-span partial logits (18 each)
__device__ int   g_flag[NSP];          // span-ready flags (reset each call)

static __device__ __forceinline__ void vmax(float4& a, const float4 b) {
    a.x = fmaxf(a.x, b.x);
    a.y = fmaxf(a.y, b.y);
    a.z = fmaxf(a.z, b.z);
    a.w = fmaxf(a.w, b.w);
}

// ---------------------------------------------------------------------------
// Reset kernel: runs FIRST each call so flag state is deterministic per
// launch and safe across graph replays.
// ---------------------------------------------------------------------------
__global__ void reset_flags_kernel() {
    int t = blockIdx.x * blockDim.x + threadIdx.x;
    if (t < NSP) g_flag[t] = 0;
}

// ---------------------------------------------------------------------------
// Fused kernel. Blocks 0..511: producers (pool + part for span s, then
// release flag). Blocks 512..66047: consumers (pair p = bid-512), spin on
// the two span flags, then stream the 6KB pair row + tails (exact R1 pair).
// Producers are dispatched first (bid order) -> always resident in wave 1
// -> no deadlock. Pool/part cost hides under the consumer DRAM-write ramp.
// ---------------------------------------------------------------------------
__global__ void __launch_bounds__(192) fused_kernel(
    const float* __restrict__ word_rep,
    const int*   __restrict__ aspects,
    const int*   __restrict__ opinions,
    const float* __restrict__ Wv,
    const float* __restrict__ Wc,
    const float* __restrict__ Wp,
    const float* __restrict__ bv,
    const float* __restrict__ bc,
    const float* __restrict__ bp,
    float* __restrict__ out)
{
    int tid = threadIdx.x;                    // 0..191

    if (blockIdx.x < NSP) {
        // ================= PRODUCER: span s =================
        int s = blockIdx.x;
        const int* sp = (s < NA) ? (aspects + 2*s) : (opinions + 2*(s - NA));
        int head = sp[0];
        int w    = sp[1] - head;              // 1..40
        int c = tid;                          // float4 lane 0..191

        // Pool: exact R1 serial loop (cost hidden under consumer stream).
        const float4* wr = (const float4*)word_rep;
        float4 r = wr[(size_t)head * D4 + c];
        for (int k = 1; k < w; ++k)
            vmax(r, wr[(size_t)(head + k) * D4 + c]);
        ((float4*)g_rep)[(size_t)s * D4 + c] = r;

        // Part: identical math/order to the R1/R2 part kernel (r already in
        // registers; same values as a g_rep reload -> bit-identical).
        int d = ((s < NA) ? 0 : D) + c * 4;

        float acc[NK];
        #pragma unroll
        for (int q = 0; q < 2; ++q)
            acc[q] = r.x*Wv[(d+0)*2+q] + r.y*Wv[(d+1)*2+q]
                   + r.z*Wv[(d+2)*2+q] + r.w*Wv[(d+3)*2+q];
        #pragma unroll
        for (int q = 0; q < NCAT; ++q)
            acc[2+q] = r.x*Wc[(d+0)*NCAT+q] + r.y*Wc[(d+1)*NCAT+q]
                     + r.z*Wc[(d+2)*NCAT+q] + r.w*Wc[(d+3)*NCAT+q];
        #pragma unroll
        for (int q = 0; q < NPOL; ++q)
            acc[15+q] = r.x*Wp[(d+0)*NPOL+q] + r.y*Wp[(d+1)*NPOL+q]
                      + r.z*Wp[(d+2)*NPOL+q] + r.w*Wp[(d+3)*NPOL+q];

        #pragma unroll
        for (int q = 0; q < NK; ++q)
            #pragma unroll
            for (int off = 16; off > 0; off >>= 1)
                acc[q] += __shfl_xor_sync(0xFFFFFFFFu, acc[q], off);

        __shared__ float sred[6][NK];
        int warp = tid >> 5;
        if ((tid & 31) == 0) {
            #pragma unroll
            for (int q = 0; q < NK; ++q) sred[warp][q] = acc[q];
        }
        __syncthreads();
        if (tid < NK) {
            float t = 0.f;
            #pragma unroll
            for (int wv = 0; wv < 6; ++wv) t += sred[wv][tid];  // fixed order
            g_part[s * NK + tid] = t;
        }

        // Release: all block writes done -> fence -> set flag.
        __syncthreads();
        if (tid == 0) {
            __threadfence();
            atomicExch(&g_flag[s], 1);
        }
    } else {
        // ================= CONSUMER: pair p =================
        int p = blockIdx.x - NSP;
        int i = p >> 8;            // aspect id
        int j = p & 255;           // opinion id

        // Acquire both span flags.
        if (tid == 0) {
            while (atomicAdd(&g_flag[i], 0) == 0) __nanosleep(100);
            while (atomicAdd(&g_flag[NA + j], 0) == 0) __nanosleep(100);
            __threadfence();
        }
        __syncthreads();

        const float* pa = g_part + i * NK;
        const float* po = g_part + (NA + j) * NK;

        float v0 = pa[0] + po[0] + bv[0];
        float v1 = pa[1] + po[1] + bv[1];
        bool m = v0 > v1;

        const float4* ar = ((const float4*)g_rep) + (size_t)i        * D4;
        const float4* op = ((const float4*)g_rep) + (size_t)(NA + j) * D4;
        float4* outp = ((float4*)out) + (size_t)p * (2 * D4);

        const float4 z4 = make_float4(0.f, 0.f, 0.f, 0.f);
        #pragma unroll
        for (int it = 0; it < 2; ++it) {
            int c = tid + it * 192;              // 0..383
            float4 v = z4;
            if (m) v = (c < D4) ? ar[c] : op[c - D4];
            __stcs(&outp[c], v);
        }

        if (tid < NCAT)
            out[OFF_CAT + (size_t)p * NCAT + tid] = m ? (pa[2 + tid] + po[2 + tid] + bc[tid]) : 0.f;
        if (tid >= 32 && tid < 32 + NPOL) {
            int k = tid - 32;
            out[OFF_POL + (size_t)p * NPOL + k] = m ? (pa[15 + k] + po[15 + k] + bp[k]) : 0.f;
        }
        if (tid == 64) {
            out[OFF_AID + p] = m ? (float)i : -1.f;
            out[OFF_OID + p] = m ? (float)j : -1.f;
            out[OFF_MSK + p] = m ? 1.f : 0.f;
        }
    }
}

// ---------------------------------------------------------------------------
extern "C" void kernel_launch(void* const* d_in, const int* in_sizes, int n_in,
                              void* d_out, int out_size)
{
    const float* word_rep = (const float*)d_in[0];   // (S, D)
    const int*   aspects  = (const int*)  d_in[1];   // (NA, 2)
    const int*   opinions = (const int*)  d_in[2];   // (NO, 2)
    const float* W_valid  = (const float*)d_in[3];   // (2D, 2)
    const float* b_valid  = (const float*)d_in[4];   // (2,)
    const float* W_cat    = (const float*)d_in[5];   // (2D, 13)
    const float* b_cat    = (const float*)d_in[6];   // (13,)
    const float* W_pol    = (const float*)d_in[7];   // (2D, 3)
    const float* b_pol    = (const float*)d_in[8];   // (3,)
    float* out = (float*)d_out;

    reset_flags_kernel<<<2, 256>>>();
    fused_kernel<<<NSP + NP, 192>>>(word_rep, aspects, opinions,
                                    W_valid, W_cat, W_pol,
                                    b_valid, b_cat, b_pol, out);
}

// round 17
// speedup vs baseline: 1.6592x; 1.6592x over previous
#include <cuda_runtime.h>
#include <cfloat>

// Problem constants
#define S    8192
#define D    768
#define D4   (D/4)        // 192 float4 per row
#define NA   256
#define NO   256
#define NSP  (NA+NO)      // 512 spans
#define NP   (NA*NO)      // 65536 pairs
#define NCAT 13
#define NPOL 3
#define NK   18           // 2 valid + 13 cat + 3 pol partials per span
#define RG   2            // row groups (384-thread blocks -> still ONE wave)
#define RP   20           // rows per group (2*20 = 40 = MAXW)

// Output layout (flattened tuple, fp32)
#define OFF_AID ((size_t)NP * (2*D))
#define OFF_OID (OFF_AID + NP)
#define OFF_CAT (OFF_OID + NP)
#define OFF_POL (OFF_CAT + (size_t)NP*NCAT)
#define OFF_MSK (OFF_POL + (size_t)NP*NPOL)

// Scratch (allocation-free rule: device globals)
__device__ float g_rep[NSP * D];       // aspect rows [0,256), opinion rows [256,512)
__device__ float g_part[NSP * NK];     // per-span partial logits (18 each)

static __device__ __forceinline__ void vmax(float4& a, const float4 b) {
    a.x = fmaxf(a.x, b.x);
    a.y = fmaxf(a.y, b.y);
    a.z = fmaxf(a.z, b.z);
    a.w = fmaxf(a.w, b.w);
}

// ---------------------------------------------------------------------------
// Kernel A: span max-pool, 2 row-groups x 192 columns = 384 threads/block.
// 12 warps/block -> 5 blocks/SM -> all 512 blocks resident in ONE wave
// (R15's 960-thread version silently needed 2 waves — that confound is
// removed here). Dependent-load chain drops 40 -> <=20. Group maxima merge
// via smem in fixed order; empty group contributes -FLT_MAX (the
// reference's fill value) -> bit-identical result.
// ---------------------------------------------------------------------------
__global__ void __launch_bounds__(RG * 192) span_pool_kernel(
    const float* __restrict__ word_rep,
    const int*   __restrict__ aspects,
    const int*   __restrict__ opinions)
{
    int s = blockIdx.x;                       // 0..511
    const int* sp = (s < NA) ? (aspects + 2*s) : (opinions + 2*(s - NA));
    int head = sp[0];
    int w    = sp[1] - head;                  // 1..40

    int tid = threadIdx.x;                    // 0..383
    int r = tid / 192;                        // row group 0..1
    int c = tid - r * 192;                    // float4 column 0..191

    __shared__ float4 sm[192];

    const float4* base = (const float4*)word_rep + (size_t)head * D4 + c;

    int k0 = r * RP;
    int k1 = min(w, k0 + RP);
    float4 m = make_float4(-FLT_MAX, -FLT_MAX, -FLT_MAX, -FLT_MAX);
    if (k0 < k1) {
        m = base[(size_t)k0 * D4];
        for (int k = k0 + 1; k < k1; ++k)
            vmax(m, base[(size_t)k * D4]);
    }
    if (r == 1) sm[c] = m;
    __syncthreads();
    if (r == 0) {
        vmax(m, sm[c]);                        // fixed order (group0, group1)
        ((float4*)g_rep)[(size_t)s * D4 + c] = m;
    }
}

// ---------------------------------------------------------------------------
// Kernel B: per-span partial logits (identical to R1 — deterministic order).
// ---------------------------------------------------------------------------
__global__ void __launch_bounds__(192) part_kernel(
    const float* __restrict__ Wv,   // (2D, 2)   row-major
    const float* __restrict__ Wc,   // (2D, 13)
    const float* __restrict__ Wp)   // (2D, 3)
{
    int s = blockIdx.x;                       // 0..511
    int rowoff = (s < NA) ? 0 : D;
    int tid = threadIdx.x;                    // 0..191

    float4 r = ((const float4*)g_rep)[(size_t)s * D4 + tid];
    int d = rowoff + tid * 4;

    float acc[NK];
    #pragma unroll
    for (int c = 0; c < 2; ++c)
        acc[c] = r.x*Wv[(d+0)*2+c] + r.y*Wv[(d+1)*2+c]
               + r.z*Wv[(d+2)*2+c] + r.w*Wv[(d+3)*2+c];
    #pragma unroll
    for (int c = 0; c < NCAT; ++c)
        acc[2+c] = r.x*Wc[(d+0)*NCAT+c] + r.y*Wc[(d+1)*NCAT+c]
                 + r.z*Wc[(d+2)*NCAT+c] + r.w*Wc[(d+3)*NCAT+c];
    #pragma unroll
    for (int c = 0; c < NPOL; ++c)
        acc[15+c] = r.x*Wp[(d+0)*NPOL+c] + r.y*Wp[(d+1)*NPOL+c]
                  + r.z*Wp[(d+2)*NPOL+c] + r.w*Wp[(d+3)*NPOL+c];

    #pragma unroll
    for (int k = 0; k < NK; ++k)
        #pragma unroll
        for (int off = 16; off > 0; off >>= 1)
            acc[k] += __shfl_xor_sync(0xFFFFFFFFu, acc[k], off);

    __shared__ float sred[6][NK];
    int warp = tid >> 5;
    if ((tid & 31) == 0) {
        #pragma unroll
        for (int k = 0; k < NK; ++k) sred[warp][k] = acc[k];
    }
    __syncthreads();
    if (tid < NK) {
        float t = 0.f;
        #pragma unroll
        for (int w = 0; w < 6; ++w) t += sred[w][tid];   // fixed order
        g_part[s * NK + tid] = t;
    }
}

// ---------------------------------------------------------------------------
// Kernel C: EXACT R1 pair kernel. One block per pair, 128 threads,
// contiguous 6KB write per block, __stcs streaming stores.
// ---------------------------------------------------------------------------
__global__ void __launch_bounds__(128) pair_kernel(
    const float* __restrict__ bv,
    const float* __restrict__ bc,
    const float* __restrict__ bp,
    float* __restrict__ out)
{
    int p = blockIdx.x;
    int i = p >> 8;            // aspect id
    int j = p & 255;           // opinion id

    const float* pa = g_part + i * NK;
    const float* po = g_part + (NA + j) * NK;

    float v0 = pa[0] + po[0] + bv[0];
    float v1 = pa[1] + po[1] + bv[1];
    bool m = v0 > v1;

    int t = threadIdx.x;
    const float4* ar = ((const float4*)g_rep) + (size_t)i        * D4;
    const float4* op = ((const float4*)g_rep) + (size_t)(NA + j) * D4;
    float4* outp = ((float4*)out) + (size_t)p * (2 * D4);

    const float4 z4 = make_float4(0.f, 0.f, 0.f, 0.f);
    #pragma unroll
    for (int it = 0; it < 3; ++it) {
        int c = t + it * 128;                // 0..383
        float4 v = z4;
        if (m) v = (c < D4) ? ar[c] : op[c - D4];
        __stcs(&outp[c], v);
    }

    if (t < NCAT)
        out[OFF_CAT + (size_t)p * NCAT + t] = m ? (pa[2 + t] + po[2 + t] + bc[t]) : 0.f;
    if (t >= 32 && t < 32 + NPOL) {
        int k = t - 32;
        out[OFF_POL + (size_t)p * NPOL + k] = m ? (pa[15 + k] + po[15 + k] + bp[k]) : 0.f;
    }
    if (t == 64) {
        out[OFF_AID + p] = m ? (float)i : -1.f;
        out[OFF_OID + p] = m ? (float)j : -1.f;
        out[OFF_MSK + p] = m ? 1.f : 0.f;
    }
}

// ---------------------------------------------------------------------------
extern "C" void kernel_launch(void* const* d_in, const int* in_sizes, int n_in,
                              void* d_out, int out_size)
{
    const float* word_rep = (const float*)d_in[0];   // (S, D)
    const int*   aspects  = (const int*)  d_in[1];   // (NA, 2)
    const int*   opinions = (const int*)  d_in[2];   // (NO, 2)
    const float* W_valid  = (const float*)d_in[3];   // (2D, 2)
    const float* b_valid  = (const float*)d_in[4];   // (2,)
    const float* W_cat    = (const float*)d_in[5];   // (2D, 13)
    const float* b_cat    = (const float*)d_in[6];   // (13,)
    const float* W_pol    = (const float*)d_in[7];   // (2D, 3)
    const float* b_pol    = (const float*)d_in[8];   // (3,)
    float* out = (float*)d_out;

    span_pool_kernel<<<NSP, RG * 192>>>(word_rep, aspects, opinions);
    part_kernel     <<<NSP, 192>>>(W_valid, W_cat, W_pol);
    pair_kernel     <<<NP, 128>>>(b_valid, b_cat, b_pol, out);
}